// round 2
// baseline (speedup 1.0000x reference)
#include <cuda_runtime.h>
#include <math.h>

// Problem constants
#define Bb 64
#define Ll 128
#define Ee 512
#define Hh 512
#define Vv 32000
#define Tt 127
#define MR (Tt*Bb)      // 8128 rows (t,b)
#define MP 8192         // padded rows for 128-tile vocab GEMM

// Output layout: [loss(1)] [attns T*B*L] [h_fin B*H] [logits B*V]
#define OFF_ATTN 1L
#define OFF_HF   (1L + (long)Tt*Bb*Ll)          // 1040385
#define OFF_LOG  (OFF_HF + (long)Bb*Hh)         // 1073153

// ---------------- scratch (static device globals; no allocs) ----------------
__device__ float g_xseq[MR*Ee];          // x_seq   [m=(t,b), E]
__device__ float g_decin[MR*Ee];         // dec_in  [m, E]
__device__ float g_gi[(long)MR*3*Hh];    // gi      [m, 3H]
__device__ float g_attnx[MR*Ll];         // dec_in part of attn logits (+b_attn)
__device__ float g_hseq[(long)MP*Hh];    // h after each step; rows >= MR zero
__device__ float g_h0[Bb*Hh];            // zeros
__device__ float g_ghpart[4*Bb*3*Hh];    // split-K partials of h @ W_hh^T
__device__ float g_wattnT[Hh*Ll];        // W_attn[:,512:] transposed [k][l]
__device__ float g_lse_m[(long)MP*256];  // per-row per-chunk max
__device__ float g_lse_s[(long)MP*256];  // per-row per-chunk sumexp
__device__ float g_ztgt[MP];             // logit at target index per row
__device__ float g_ce[MR];               // per-row cross entropy

// ---------------- init: zero h0 + pad rows, transpose W_attn h-part ---------
__global__ void k_init(const float* __restrict__ W_attn) {
    int idx = blockIdx.x * blockDim.x + threadIdx.x;  // 65536 threads
    if (idx < Bb*Hh) g_h0[idx] = 0.f;
    if (idx < (MP-MR)*Hh) g_hseq[(long)MR*Hh + idx] = 0.f;
    if (idx < Hh*Ll) {
        int k = idx >> 7, l = idx & 127;
        g_wattnT[idx] = W_attn[l*(2*Hh) + Hh + k];
    }
}

// ---------------- embedding gather: x_seq + dec_in_seq ----------------------
__global__ void k_embed(const int* __restrict__ dec, const float* __restrict__ emb) {
    int m = blockIdx.x;            // 0..MR-1
    int t = m / Bb, b = m % Bb;
    int tok_x = dec[b*Ll + t];
    int tp = (t > 0) ? (t - 1) : 0;
    int tok_d = dec[b*Ll + tp];
    const float4* ex = (const float4*)(emb + (long)tok_x * Ee);
    const float4* ed = (const float4*)(emb + (long)tok_d * Ee);
    float4* ox = (float4*)(g_xseq + (long)m * Ee);
    float4* od = (float4*)(g_decin + (long)m * Ee);
    int i = threadIdx.x;           // 128 threads, 512/4 = 128 float4
    ox[i] = ex[i];
    od[i] = ed[i];
}

// ---------------- generic fp32 SGEMM body: C = A * B^T (+bias) --------------
// BM=BN=64, BK=16, 256 threads, 4x4 micro-tile. gridDim.z = split-K slices.
__device__ __forceinline__ void sgemm_body(
    const float* __restrict__ A, int lda,
    const float* __restrict__ Bm, int ldb,
    const float* __restrict__ bias,
    float* __restrict__ C, int ldc, int K)
{
    __shared__ float As[16][68];
    __shared__ float Bs[16][68];
    int tid = threadIdx.x;
    int tx = tid & 15, ty = tid >> 4;
    int m0 = blockIdx.y * 64, n0 = blockIdx.x * 64;
    int ks = K / gridDim.z;
    int k0 = blockIdx.z * ks;
    int lr = tid >> 2;
    int lc = (tid & 3) << 2;
    float acc[4][4] = {};
    const float* Ap = A + (long)(m0 + lr) * lda + lc;
    const float* Bp = Bm + (long)(n0 + lr) * ldb + lc;
    for (int kk = k0; kk < k0 + ks; kk += 16) {
        float4 av = *(const float4*)(Ap + kk);
        float4 bv = *(const float4*)(Bp + kk);
        As[lc+0][lr]=av.x; As[lc+1][lr]=av.y; As[lc+2][lr]=av.z; As[lc+3][lr]=av.w;
        Bs[lc+0][lr]=bv.x; Bs[lc+1][lr]=bv.y; Bs[lc+2][lr]=bv.z; Bs[lc+3][lr]=bv.w;
        __syncthreads();
        #pragma unroll
        for (int k = 0; k < 16; k++) {
            float4 a4 = *(const float4*)&As[k][ty*4];
            float4 b4 = *(const float4*)&Bs[k][tx*4];
            float aa[4] = {a4.x, a4.y, a4.z, a4.w};
            float bb[4] = {b4.x, b4.y, b4.z, b4.w};
            #pragma unroll
            for (int i = 0; i < 4; i++)
                #pragma unroll
                for (int j = 0; j < 4; j++)
                    acc[i][j] += aa[i] * bb[j];
        }
        __syncthreads();
    }
    float* Cp = C + (long)blockIdx.z * (long)gridDim.y * 64 * ldc;
    #pragma unroll
    for (int i = 0; i < 4; i++) {
        int m = m0 + ty*4 + i;
        #pragma unroll
        for (int j = 0; j < 4; j++) {
            int n = n0 + tx*4 + j;
            float v = acc[i][j];
            if (bias) v += bias[n];
            Cp[(long)m * ldc + n] = v;
        }
    }
}

__global__ void k_gi(const float* __restrict__ W_ih, const float* __restrict__ b_ih) {
    sgemm_body(g_xseq, Ee, W_ih, Ee, b_ih, g_gi, 3*Hh, Ee);
}
__global__ void k_attnx(const float* __restrict__ W_attn, const float* __restrict__ b_attn) {
    sgemm_body(g_decin, Ee, W_attn, 2*Hh, b_attn, g_attnx, Ll, Ee);
}
__global__ void k_gh(const float* __restrict__ W_hh, int t) {
    const float* hp = (t == 0) ? g_h0 : (g_hseq + (long)(t-1)*Bb*Hh);
    sgemm_body(hp, Hh, W_hh, Hh, nullptr, g_ghpart, 3*Hh, Hh);
}

// ---------------- per-step: GRU gates (blocks 0..63) + attention (64..127) --
__global__ void k_step2(int t, const float* __restrict__ b_hh, float* __restrict__ out) {
    __shared__ float hs[Hh];
    __shared__ float part[4][Ll];
    __shared__ float r2[Ll];
    const float* hp = (t == 0) ? g_h0 : (g_hseq + (long)(t-1)*Bb*Hh);
    int blk = blockIdx.x, tid = threadIdx.x;  // 512 threads
    if (blk < Bb) {
        // GRU gates for batch row b, hidden index j
        int b = blk, j = tid;
        long gb = (long)b * (3*Hh);
        float hr = g_ghpart[gb + j]          + g_ghpart[98304 + gb + j]
                 + g_ghpart[2*98304 + gb + j]+ g_ghpart[3*98304 + gb + j] + b_hh[j];
        float hz = g_ghpart[gb + Hh + j]          + g_ghpart[98304 + gb + Hh + j]
                 + g_ghpart[2*98304 + gb + Hh + j]+ g_ghpart[3*98304 + gb + Hh + j] + b_hh[Hh + j];
        float hn = g_ghpart[gb + 2*Hh + j]          + g_ghpart[98304 + gb + 2*Hh + j]
                 + g_ghpart[2*98304 + gb + 2*Hh + j]+ g_ghpart[3*98304 + gb + 2*Hh + j] + b_hh[2*Hh + j];
        long gib = (long)(t*Bb + b) * (3*Hh);
        float r = 1.f / (1.f + expf(-(g_gi[gib + j] + hr)));
        float z = 1.f / (1.f + expf(-(g_gi[gib + Hh + j] + hz)));
        float n = tanhf(g_gi[gib + 2*Hh + j] + r * hn);
        float hprev = hp[b*Hh + j];
        g_hseq[(long)(t*Bb + b) * Hh + j] = (1.f - z) * n + z * hprev;
    } else {
        // attention logits (h half) + softmax -> attns output
        int b = blk - Bb;
        hs[tid] = hp[b*Hh + tid];
        __syncthreads();
        int l = tid & 127, p = tid >> 7;    // p in 0..3, k-chunk of 128
        float s = 0.f;
        const float* wt = g_wattnT + p*128*Ll + l;
        const float* hh = hs + p*128;
        #pragma unroll 8
        for (int k = 0; k < 128; k++) s += hh[k] * wt[k*Ll];
        part[p][l] = s;
        __syncthreads();
        float logit = -1e30f;
        if (tid < 128) {
            logit = part[0][tid] + part[1][tid] + part[2][tid] + part[3][tid]
                  + g_attnx[(long)(t*Bb + b)*Ll + tid];
            r2[tid] = logit;
        }
        __syncthreads();
        for (int off = 64; off > 0; off >>= 1) {
            if (tid < off) r2[tid] = fmaxf(r2[tid], r2[tid + off]);
            __syncthreads();
        }
        float mx = r2[0];
        __syncthreads();
        float e = (tid < 128) ? expf(logit - mx) : 0.f;
        if (tid < 128) r2[tid] = e;
        __syncthreads();
        for (int off = 64; off > 0; off >>= 1) {
            if (tid < off) r2[tid] += r2[tid + off];
            __syncthreads();
        }
        if (tid < 128) out[OFF_ATTN + ((long)t*Bb + b)*Ll + tid] = e / r2[0];
    }
}

// ---------------- copy final hidden state ------------------------------------
__global__ void k_hfin(float* __restrict__ out) {
    int b = blockIdx.x, j = threadIdx.x;
    out[OFF_HF + (long)b*Hh + j] = g_hseq[(long)((Tt-1)*Bb + b)*Hh + j];
}

// ---------------- vocab GEMM + fused online logsumexp epilogue --------------
// C[8192p x 32000] = h_seq @ W_out^T + b_out. BM=BN=128, BK=16, 8x8 micro.
__global__ void __launch_bounds__(256)
k_vocab(const float* __restrict__ W_out, const float* __restrict__ b_out,
        const int* __restrict__ dec, float* __restrict__ out)
{
    __shared__ float As[16][132];
    __shared__ float Bs[16][132];
    int tid = threadIdx.x;
    int tx = tid & 15, ty = tid >> 4;
    int m0 = blockIdx.y * 128, n0 = blockIdx.x * 128;
    int lr = tid >> 2;
    int lc = (tid & 3) << 2;
    float acc[8][8] = {};
    for (int kk = 0; kk < Hh; kk += 16) {
        #pragma unroll
        for (int r = 0; r < 2; r++) {
            int row = lr + r*64;
            float4 av = *(const float4*)(g_hseq + (long)(m0 + row)*Hh + kk + lc);
            float4 bv = *(const float4*)(W_out + (long)(n0 + row)*Hh + kk + lc);
            As[lc+0][row]=av.x; As[lc+1][row]=av.y; As[lc+2][row]=av.z; As[lc+3][row]=av.w;
            Bs[lc+0][row]=bv.x; Bs[lc+1][row]=bv.y; Bs[lc+2][row]=bv.z; Bs[lc+3][row]=bv.w;
        }
        __syncthreads();
        #pragma unroll
        for (int k = 0; k < 16; k++) {
            float4 a0 = *(const float4*)&As[k][ty*8];
            float4 a1 = *(const float4*)&As[k][ty*8 + 4];
            float4 b0 = *(const float4*)&Bs[k][tx*8];
            float4 b1 = *(const float4*)&Bs[k][tx*8 + 4];
            float aa[8] = {a0.x,a0.y,a0.z,a0.w,a1.x,a1.y,a1.z,a1.w};
            float bb[8] = {b0.x,b0.y,b0.z,b0.w,b1.x,b1.y,b1.z,b1.w};
            #pragma unroll
            for (int i = 0; i < 8; i++)
                #pragma unroll
                for (int j = 0; j < 8; j++)
                    acc[i][j] += aa[i] * bb[j];
        }
        __syncthreads();
    }
    // bias
    float bj[8];
    #pragma unroll
    for (int j = 0; j < 8; j++) bj[j] = b_out[n0 + tx*8 + j];
    #pragma unroll
    for (int i = 0; i < 8; i++)
        #pragma unroll
        for (int j = 0; j < 8; j++) acc[i][j] += bj[j];

    // epilogue: per-row chunk max/sumexp, target gather, last-step logits
    int chunk = blockIdx.x;
    #pragma unroll
    for (int i = 0; i < 8; i++) {
        int mg = m0 + ty*8 + i;
        bool valid = (mg < MR);
        float mx = -1e30f;
        #pragma unroll
        for (int j = 0; j < 8; j++) mx = fmaxf(mx, acc[i][j]);
        #pragma unroll
        for (int off = 8; off > 0; off >>= 1)
            mx = fmaxf(mx, __shfl_xor_sync(0xffffffffu, mx, off));
        float se = 0.f;
        #pragma unroll
        for (int j = 0; j < 8; j++) se += expf(acc[i][j] - mx);
        #pragma unroll
        for (int off = 8; off > 0; off >>= 1)
            se += __shfl_xor_sync(0xffffffffu, se, off);
        if (valid && tx == 0) {
            g_lse_m[(long)mg*256 + chunk] = mx;
            g_lse_s[(long)mg*256 + chunk] = se;
        }
        if (valid) {
            int t = mg >> 6, b = mg & 63;
            int tgt = dec[b*Ll + t];
            int loc = tgt - n0;
            if (loc >= 0 && loc < 128 && (loc >> 3) == tx)
                g_ztgt[mg] = acc[i][loc & 7];
            if (t == Tt - 1) {
                float* lo = out + OFF_LOG + (long)b*Vv + n0 + tx*8;
                #pragma unroll
                for (int j = 0; j < 8; j++) lo[j] = acc[i][j];
            }
        }
    }
}

// ---------------- combine chunk (m,s) -> per-row CE --------------------------
__global__ void k_rowce() {
    int m = blockIdx.x * 128 + threadIdx.x;
    if (m >= MR) return;
    float M = -1e30f, S = 0.f;
    for (int c = 0; c < 250; c++) {
        float mc = g_lse_m[(long)m*256 + c];
        float sc = g_lse_s[(long)m*256 + c];
        float Mn = fmaxf(M, mc);
        S = S * expf(M - Mn) + sc * expf(mc - Mn);
        M = Mn;
    }
    g_ce[m] = (M + logf(S)) - g_ztgt[m];
}

__global__ void k_loss(float* __restrict__ out) {
    __shared__ float red[256];
    float s = 0.f;
    for (int m = threadIdx.x; m < MR; m += 256) s += g_ce[m];
    red[threadIdx.x] = s;
    __syncthreads();
    for (int off = 128; off > 0; off >>= 1) {
        if (threadIdx.x < off) red[threadIdx.x] += red[threadIdx.x + off];
        __syncthreads();
    }
    if (threadIdx.x == 0) out[0] = red[0] / (float)Bb;
}

// ---------------- launcher ----------------------------------------------------
extern "C" void kernel_launch(void* const* d_in, const int* in_sizes, int n_in,
                              void* d_out, int out_size) {
    (void)in_sizes; (void)n_in; (void)out_size;
    const int*   dec    = (const int*)d_in[0];
    // d_in[1] hidden: ignored (zeroed in forward); d_in[2] encoder_outputs: dead code
    const float* emb    = (const float*)d_in[3];
    const float* W_attn = (const float*)d_in[4];
    const float* b_attn = (const float*)d_in[5];
    const float* W_ih   = (const float*)d_in[6];
    const float* W_hh   = (const float*)d_in[7];
    const float* b_ih   = (const float*)d_in[8];
    const float* b_hh   = (const float*)d_in[9];
    const float* W_out  = (const float*)d_in[10];
    const float* b_out  = (const float*)d_in[11];
    float* out = (float*)d_out;

    k_init<<<64, 1024>>>(W_attn);
    k_embed<<<MR, 128>>>(dec, emb);
    k_gi<<<dim3(24, 127, 1), 256>>>(W_ih, b_ih);
    k_attnx<<<dim3(2, 127, 1), 256>>>(W_attn, b_attn);
    for (int t = 0; t < Tt; t++) {
        k_gh<<<dim3(24, 1, 4), 256>>>(W_hh, t);
        k_step2<<<128, 512>>>(t, b_hh, out);
    }
    k_hfin<<<64, 512>>>(out);
    k_vocab<<<dim3(250, 64), 256>>>(W_out, b_out, dec, out);
    k_rowce<<<64, 128>>>();
    k_loss<<<1, 256>>>(out);
}

// round 5
// speedup vs baseline: 2.0527x; 2.0527x over previous
#include <cuda_runtime.h>
#include <math.h>

// Problem constants
#define Bb 64
#define Ll 128
#define Ee 512
#define Hh 512
#define Vv 32000
#define Tt 127
#define MR (Tt*Bb)      // 8128 rows (t,b)
#define MP 8192         // padded rows for 128-tile vocab GEMM

// Output layout: [loss(1)] [attns T*B*L] [h_fin B*H] [logits B*V]
#define OFF_ATTN 1L
#define OFF_HF   (1L + (long)Tt*Bb*Ll)
#define OFF_LOG  (OFF_HF + (long)Bb*Hh)

// ---------------- scratch (static device globals; no allocs) ----------------
__device__ float g_xseq[(long)MR*Ee];    // x_seq   [m=(t,b), E]
__device__ float g_decin[(long)MR*Ee];   // dec_in  [m, E]
__device__ float g_gi[(long)MR*3*Hh];    // gi      [m, 3H]
__device__ float g_attnx[MR*Ll];         // dec_in part of attn logits (+b_attn)
__device__ float g_hseq[(long)MP*Hh];    // h after each step; rows >= MR zero
__device__ float g_h0[Bb*Hh];            // zeros
__device__ float g_ghpart[4*Bb*3*Hh];    // split-K partials of h @ W_hh^T
__device__ float g_wattnT[Hh*Ll];        // W_attn[:,512:] transposed [k][l]
__device__ float g_lse_m[(long)MP*256];  // per-row per-chunk max
__device__ float g_lse_s[(long)MP*256];  // per-row per-chunk sumexp
__device__ float g_ztgt[MP];             // logit at target index per row
__device__ float g_ce[MR];               // per-row cross entropy

// ---------------- helpers ----------------------------------------------------
__device__ __forceinline__ unsigned f2tf32(float x) {
    unsigned y;
    asm("cvt.rna.tf32.f32 %0, %1;" : "=r"(y) : "f"(x));
    return y;
}

__device__ __forceinline__ void mma_tf32(float d[4], const unsigned a[4],
                                         const unsigned b[2], const float c[4]) {
    asm volatile(
        "mma.sync.aligned.m16n8k8.row.col.f32.tf32.tf32.f32 "
        "{%0,%1,%2,%3},{%4,%5,%6,%7},{%8,%9},{%10,%11,%12,%13};"
        : "=f"(d[0]), "=f"(d[1]), "=f"(d[2]), "=f"(d[3])
        : "r"(a[0]), "r"(a[1]), "r"(a[2]), "r"(a[3]),
          "r"(b[0]), "r"(b[1]),
          "f"(c[0]), "f"(c[1]), "f"(c[2]), "f"(c[3]));
}

// ---------------- init: zero h0 + pad rows, transpose W_attn h-part ---------
__global__ void k_init(const float* __restrict__ W_attn) {
    int idx = blockIdx.x * blockDim.x + threadIdx.x;  // 65536 threads
    if (idx < Bb*Hh) g_h0[idx] = 0.f;
    if (idx < (MP-MR)*Hh) g_hseq[(long)MR*Hh + idx] = 0.f;
    if (idx < Hh*Ll) {
        int k = idx >> 7, l = idx & 127;
        g_wattnT[idx] = W_attn[l*(2*Hh) + Hh + k];
    }
}

// ---------------- embedding gather: x_seq + dec_in_seq ----------------------
__global__ void k_embed(const int* __restrict__ dec, const float* __restrict__ emb) {
    int m = blockIdx.x;            // 0..MR-1
    int t = m / Bb, b = m % Bb;
    int tok_x = dec[b*Ll + t];
    int tp = (t > 0) ? (t - 1) : 0;
    int tok_d = dec[b*Ll + tp];
    const float4* ex = (const float4*)(emb + (long)tok_x * Ee);
    const float4* ed = (const float4*)(emb + (long)tok_d * Ee);
    float4* ox = (float4*)(g_xseq + (long)m * Ee);
    float4* od = (float4*)(g_decin + (long)m * Ee);
    int i = threadIdx.x;           // 128 threads, 512/4 = 128 float4
    ox[i] = ex[i];
    od[i] = ed[i];
}

// ---------------- generic fp32 SGEMM body: C = A * B^T (+bias) --------------
// BM=BN=64, BK=16, 256 threads, 4x4 micro-tile. gridDim.z = split-K slices.
__device__ __forceinline__ void sgemm_body(
    const float* __restrict__ A, int lda,
    const float* __restrict__ Bm, int ldb,
    const float* __restrict__ bias,
    float* __restrict__ C, long ldc, int K)
{
    __shared__ float As[16][68];
    __shared__ float Bs[16][68];
    int tid = threadIdx.x;
    int tx = tid & 15, ty = tid >> 4;
    int m0 = blockIdx.y * 64, n0 = blockIdx.x * 64;
    int ks = K / gridDim.z;
    int k0 = blockIdx.z * ks;
    int lr = tid >> 2;
    int lc = (tid & 3) << 2;
    float acc[4][4] = {};
    const float* Ap = A + (long)(m0 + lr) * lda + lc;
    const float* Bp = Bm + (long)(n0 + lr) * ldb + lc;
    for (int kk = k0; kk < k0 + ks; kk += 16) {
        float4 av = *(const float4*)(Ap + kk);
        float4 bv = *(const float4*)(Bp + kk);
        As[lc+0][lr]=av.x; As[lc+1][lr]=av.y; As[lc+2][lr]=av.z; As[lc+3][lr]=av.w;
        Bs[lc+0][lr]=bv.x; Bs[lc+1][lr]=bv.y; Bs[lc+2][lr]=bv.z; Bs[lc+3][lr]=bv.w;
        __syncthreads();
        #pragma unroll
        for (int k = 0; k < 16; k++) {
            float4 a4 = *(const float4*)&As[k][ty*4];
            float4 b4 = *(const float4*)&Bs[k][tx*4];
            float aa[4] = {a4.x, a4.y, a4.z, a4.w};
            float bb[4] = {b4.x, b4.y, b4.z, b4.w};
            #pragma unroll
            for (int i = 0; i < 4; i++)
                #pragma unroll
                for (int j = 0; j < 4; j++)
                    acc[i][j] += aa[i] * bb[j];
        }
        __syncthreads();
    }
    float* Cp = C + (long)blockIdx.z * (long)gridDim.y * 64 * ldc;
    #pragma unroll
    for (int i = 0; i < 4; i++) {
        int m = m0 + ty*4 + i;
        #pragma unroll
        for (int j = 0; j < 4; j++) {
            int n = n0 + tx*4 + j;
            float v = acc[i][j];
            if (bias) v += bias[n];
            Cp[(long)m * ldc + n] = v;
        }
    }
}

__global__ void k_gi(const float* __restrict__ W_ih, const float* __restrict__ b_ih) {
    sgemm_body(g_xseq, Ee, W_ih, Ee, b_ih, g_gi, 3*Hh, Ee);
}
__global__ void k_attnx(const float* __restrict__ W_attn, const float* __restrict__ b_attn) {
    sgemm_body(g_decin, Ee, W_attn, 2*Hh, b_attn, g_attnx, Ll, Ee);
}
__global__ void k_gh(const float* __restrict__ W_hh, int t) {
    const float* hp = (t == 0) ? g_h0 : (g_hseq + (long)(t-1)*Bb*Hh);
    sgemm_body(hp, Hh, W_hh, Hh, nullptr, g_ghpart, 3*Hh, Hh);
}
// final-step logits output: C[64 x 32000] = h_last @ W_out^T + b_out (fp32-exact)
__global__ void k_logits(const float* __restrict__ W_out, const float* __restrict__ b_out,
                         float* __restrict__ out) {
    sgemm_body(g_hseq + (long)(Tt-1)*Bb*Hh, Hh, W_out, Hh, b_out,
               out + OFF_LOG, Vv, Hh);
}

// ---------------- per-step: GRU gates (blocks 0..63) + attention (64..127) --
__global__ void k_step2(int t, const float* __restrict__ b_hh, float* __restrict__ out) {
    __shared__ float hs[Hh];
    __shared__ float part[4][Ll];
    __shared__ float r2[Ll];
    const float* hp = (t == 0) ? g_h0 : (g_hseq + (long)(t-1)*Bb*Hh);
    int blk = blockIdx.x, tid = threadIdx.x;  // 512 threads
    if (blk < Bb) {
        int b = blk, j = tid;
        long gb = (long)b * (3*Hh);
        float hr = g_ghpart[gb + j]          + g_ghpart[98304 + gb + j]
                 + g_ghpart[2*98304 + gb + j]+ g_ghpart[3*98304 + gb + j] + b_hh[j];
        float hz = g_ghpart[gb + Hh + j]          + g_ghpart[98304 + gb + Hh + j]
                 + g_ghpart[2*98304 + gb + Hh + j]+ g_ghpart[3*98304 + gb + Hh + j] + b_hh[Hh + j];
        float hn = g_ghpart[gb + 2*Hh + j]          + g_ghpart[98304 + gb + 2*Hh + j]
                 + g_ghpart[2*98304 + gb + 2*Hh + j]+ g_ghpart[3*98304 + gb + 2*Hh + j] + b_hh[2*Hh + j];
        long gib = (long)(t*Bb + b) * (3*Hh);
        float r = 1.f / (1.f + expf(-(g_gi[gib + j] + hr)));
        float z = 1.f / (1.f + expf(-(g_gi[gib + Hh + j] + hz)));
        float n = tanhf(g_gi[gib + 2*Hh + j] + r * hn);
        float hprev = hp[b*Hh + j];
        g_hseq[(long)(t*Bb + b) * Hh + j] = (1.f - z) * n + z * hprev;
    } else {
        int b = blk - Bb;
        hs[tid] = hp[b*Hh + tid];
        __syncthreads();
        int l = tid & 127, p = tid >> 7;
        float s = 0.f;
        const float* wt = g_wattnT + p*128*Ll + l;
        const float* hh = hs + p*128;
        #pragma unroll 8
        for (int k = 0; k < 128; k++) s += hh[k] * wt[k*Ll];
        part[p][l] = s;
        __syncthreads();
        float logit = -1e30f;
        if (tid < 128) {
            logit = part[0][tid] + part[1][tid] + part[2][tid] + part[3][tid]
                  + g_attnx[(long)(t*Bb + b)*Ll + tid];
            r2[tid] = logit;
        }
        __syncthreads();
        for (int off = 64; off > 0; off >>= 1) {
            if (tid < off) r2[tid] = fmaxf(r2[tid], r2[tid + off]);
            __syncthreads();
        }
        float mx = r2[0];
        __syncthreads();
        float e = (tid < 128) ? expf(logit - mx) : 0.f;
        if (tid < 128) r2[tid] = e;
        __syncthreads();
        for (int off = 64; off > 0; off >>= 1) {
            if (tid < off) r2[tid] += r2[tid + off];
            __syncthreads();
        }
        if (tid < 128) out[OFF_ATTN + ((long)t*Bb + b)*Ll + tid] = e / r2[0];
    }
}

// ---------------- copy final hidden state ------------------------------------
__global__ void k_hfin(float* __restrict__ out) {
    int b = blockIdx.x, j = threadIdx.x;
    out[OFF_HF + (long)b*Hh + j] = g_hseq[(long)((Tt-1)*Bb + b)*Hh + j];
}

// ---------------- vocab tf32 GEMM + fused online logsumexp (loss path only) --
__global__ void __launch_bounds__(256)
k_vocab(const float* __restrict__ Bw, const float* __restrict__ bias,
        const int* __restrict__ dec)
{
    __shared__ unsigned As[128][20];
    __shared__ unsigned Bs[128][20];
    __shared__ float red_m[128][4];
    __shared__ float red_s[128][4];

    int tid = threadIdx.x;
    int warp = tid >> 5, lane = tid & 31;
    int wm = warp & 1, wn = warp >> 1;
    int m0 = blockIdx.y * 128, n0 = blockIdx.x * 128;
    int qr = lane >> 2, qc = lane & 3;
    int lrow = tid >> 1, lcol = (tid & 1) * 8;

    float acc[4][4][4] = {};
    const float* Ap = g_hseq + (long)(m0 + lrow) * Hh + lcol;
    const float* Bp = Bw + (long)(n0 + lrow) * Hh + lcol;

    for (int kk = 0; kk < Hh; kk += 16) {
        float4 a0 = *(const float4*)(Ap + kk);
        float4 a1 = *(const float4*)(Ap + kk + 4);
        float4 b0 = *(const float4*)(Bp + kk);
        float4 b1 = *(const float4*)(Bp + kk + 4);
        As[lrow][lcol+0]=f2tf32(a0.x); As[lrow][lcol+1]=f2tf32(a0.y);
        As[lrow][lcol+2]=f2tf32(a0.z); As[lrow][lcol+3]=f2tf32(a0.w);
        As[lrow][lcol+4]=f2tf32(a1.x); As[lrow][lcol+5]=f2tf32(a1.y);
        As[lrow][lcol+6]=f2tf32(a1.z); As[lrow][lcol+7]=f2tf32(a1.w);
        Bs[lrow][lcol+0]=f2tf32(b0.x); Bs[lrow][lcol+1]=f2tf32(b0.y);
        Bs[lrow][lcol+2]=f2tf32(b0.z); Bs[lrow][lcol+3]=f2tf32(b0.w);
        Bs[lrow][lcol+4]=f2tf32(b1.x); Bs[lrow][lcol+5]=f2tf32(b1.y);
        Bs[lrow][lcol+6]=f2tf32(b1.z); Bs[lrow][lcol+7]=f2tf32(b1.w);
        __syncthreads();
        #pragma unroll
        for (int ks = 0; ks < 16; ks += 8) {
            unsigned af[4][4], bf[4][2];
            #pragma unroll
            for (int mi = 0; mi < 4; mi++) {
                int r = wm*64 + mi*16 + qr;
                af[mi][0] = As[r  ][ks + qc];
                af[mi][1] = As[r+8][ks + qc];
                af[mi][2] = As[r  ][ks + 4 + qc];
                af[mi][3] = As[r+8][ks + 4 + qc];
            }
            #pragma unroll
            for (int ni = 0; ni < 4; ni++) {
                int c = wn*32 + ni*8 + qr;
                bf[ni][0] = Bs[c][ks + qc];
                bf[ni][1] = Bs[c][ks + 4 + qc];
            }
            #pragma unroll
            for (int mi = 0; mi < 4; mi++)
                #pragma unroll
                for (int ni = 0; ni < 4; ni++)
                    mma_tf32(acc[mi][ni], af[mi], bf[ni], acc[mi][ni]);
        }
        __syncthreads();
    }

    // bias
    #pragma unroll
    for (int ni = 0; ni < 4; ni++) {
        int n = n0 + wn*32 + ni*8 + 2*qc;
        float bv0 = bias[n], bv1 = bias[n+1];
        #pragma unroll
        for (int mi = 0; mi < 4; mi++) {
            acc[mi][ni][0] += bv0; acc[mi][ni][1] += bv1;
            acc[mi][ni][2] += bv0; acc[mi][ni][3] += bv1;
        }
    }

    // per-row chunk max + sumexp
    #pragma unroll
    for (int mi = 0; mi < 4; mi++) {
        #pragma unroll
        for (int h = 0; h < 2; h++) {
            float mx = -1e30f;
            #pragma unroll
            for (int ni = 0; ni < 4; ni++) {
                mx = fmaxf(mx, acc[mi][ni][h*2]);
                mx = fmaxf(mx, acc[mi][ni][h*2+1]);
            }
            mx = fmaxf(mx, __shfl_xor_sync(0xffffffffu, mx, 1));
            mx = fmaxf(mx, __shfl_xor_sync(0xffffffffu, mx, 2));
            float se = 0.f;
            #pragma unroll
            for (int ni = 0; ni < 4; ni++) {
                se += expf(acc[mi][ni][h*2]   - mx);
                se += expf(acc[mi][ni][h*2+1] - mx);
            }
            se += __shfl_xor_sync(0xffffffffu, se, 1);
            se += __shfl_xor_sync(0xffffffffu, se, 2);
            if (qc == 0) {
                int lr = wm*64 + mi*16 + h*8 + qr;
                red_m[lr][wn] = mx;
                red_s[lr][wn] = se;
            }
        }
    }

    // target gather
    #pragma unroll
    for (int mi = 0; mi < 4; mi++) {
        #pragma unroll
        for (int h = 0; h < 2; h++) {
            int mg = m0 + wm*64 + mi*16 + h*8 + qr;
            if (mg < MR) {
                int t = mg >> 6, b = mg & 63;
                int tgt = dec[b*Ll + t];
                #pragma unroll
                for (int ni = 0; ni < 4; ni++) {
                    int n = n0 + wn*32 + ni*8 + 2*qc;
                    if (n == tgt)   g_ztgt[mg] = acc[mi][ni][h*2];
                    if (n+1 == tgt) g_ztgt[mg] = acc[mi][ni][h*2+1];
                }
            }
        }
    }
    __syncthreads();

    if (tid < 128) {
        int row = tid;
        float M = red_m[row][0];
        M = fmaxf(M, red_m[row][1]);
        M = fmaxf(M, red_m[row][2]);
        M = fmaxf(M, red_m[row][3]);
        float S = 0.f;
        #pragma unroll
        for (int w = 0; w < 4; w++) S += red_s[row][w] * expf(red_m[row][w] - M);
        int mg = m0 + row;
        if (mg < MR) {
            g_lse_m[(long)mg*256 + blockIdx.x] = M;
            g_lse_s[(long)mg*256 + blockIdx.x] = S;
        }
    }
}

// ---------------- combine chunk (m,s) -> per-row CE --------------------------
__global__ void k_rowce() {
    int m = blockIdx.x * 128 + threadIdx.x;
    if (m >= MR) return;
    float M = -1e30f, S = 0.f;
    for (int c = 0; c < 250; c++) {
        float mc = g_lse_m[(long)m*256 + c];
        float sc = g_lse_s[(long)m*256 + c];
        float Mn = fmaxf(M, mc);
        S = S * expf(M - Mn) + sc * expf(mc - Mn);
        M = Mn;
    }
    g_ce[m] = (M + logf(S)) - g_ztgt[m];
}

__global__ void k_loss(float* __restrict__ out) {
    __shared__ float red[256];
    float s = 0.f;
    for (int m = threadIdx.x; m < MR; m += 256) s += g_ce[m];
    red[threadIdx.x] = s;
    __syncthreads();
    for (int off = 128; off > 0; off >>= 1) {
        if (threadIdx.x < off) red[threadIdx.x] += red[threadIdx.x + off];
        __syncthreads();
    }
    if (threadIdx.x == 0) out[0] = red[0] / (float)Bb;
}

// ---------------- launcher ----------------------------------------------------
extern "C" void kernel_launch(void* const* d_in, const int* in_sizes, int n_in,
                              void* d_out, int out_size) {
    (void)in_sizes; (void)n_in; (void)out_size;
    const int*   dec    = (const int*)d_in[0];
    const float* emb    = (const float*)d_in[3];
    const float* W_attn = (const float*)d_in[4];
    const float* b_attn = (const float*)d_in[5];
    const float* W_ih   = (const float*)d_in[6];
    const float* W_hh   = (const float*)d_in[7];
    const float* b_ih   = (const float*)d_in[8];
    const float* b_hh   = (const float*)d_in[9];
    const float* W_out  = (const float*)d_in[10];
    const float* b_out  = (const float*)d_in[11];
    float* out = (float*)d_out;

    k_init<<<64, 1024>>>(W_attn);
    k_embed<<<MR, 128>>>(dec, emb);
    k_gi<<<dim3(24, 127, 1), 256>>>(W_ih, b_ih);
    k_attnx<<<dim3(2, 127, 1), 256>>>(W_attn, b_attn);
    for (int t = 0; t < Tt; t++) {
        k_gh<<<dim3(24, 1, 4), 256>>>(W_hh, t);
        k_step2<<<128, 512>>>(t, b_hh, out);
    }
    k_hfin<<<64, 512>>>(out);
    // loss path: tf32 vocab GEMM with fused online logsumexp (no logits write)
    k_vocab<<<dim3(250, 64), 256>>>(W_out, b_out, dec);
    // logits output: fp32-exact small GEMM on the last step only
    k_logits<<<dim3(500, 1, 1), 256>>>(W_out, b_out, out);
    k_rowce<<<64, 128>>>();
    k_loss<<<1, 256>>>(out);
}